// round 1
// baseline (speedup 1.0000x reference)
#include <cuda_runtime.h>
#include <math_constants.h>

// Problem constants
#define BB 32
#define NN 10000
#define DD 64
#define MM 64
#define KK 10
#define TN 128
#define NTILES ((NN + TN - 1) / TN)   // 79

// Output layout (fp32 concat): selected [B,M,K,D] | batch_indices [B,M,K] | indices [B,M,K]
#define SEL_SIZE (BB * MM * KK * DD)          // 1,310,720
#define OFF_BI   (SEL_SIZE)                   // 1,310,720
#define OFF_ID   (SEL_SIZE + BB * MM * KK)    // 1,331,200

// Scratch (static device allocations are allowed)
__device__ float g_cand_val[BB * MM * NTILES * KK];
__device__ int   g_cand_idx[BB * MM * NTILES * KK];

__device__ __forceinline__ bool cand_gt(float v1, int i1, float v2, int i2) {
    // descending by value; ties -> smaller index first (matches jax top_k)
    return (v1 > v2) || (v1 == v2 && i1 < i2);
}

__device__ __forceinline__ void insert10(float (&vals)[KK], int (&idxs)[KK], float v, int i) {
    if (cand_gt(v, i, vals[KK - 1], idxs[KK - 1])) {
        vals[KK - 1] = v;
        idxs[KK - 1] = i;
#pragma unroll
        for (int k = KK - 1; k > 0; --k) {
            if (cand_gt(vals[k], idxs[k], vals[k - 1], idxs[k - 1])) {
                float tv = vals[k]; vals[k] = vals[k - 1]; vals[k - 1] = tv;
                int   ti = idxs[k]; idxs[k] = idxs[k - 1]; idxs[k - 1] = ti;
            }
        }
    }
}

// ---------------------------------------------------------------------------
// Phase 1: per (tile, b) CTA — 64x128x64 fp32 GEMM + per-m top-10 of the tile
// ---------------------------------------------------------------------------
__global__ __launch_bounds__(128, 4)
void phase1_kernel(const float* __restrict__ feat, const float* __restrict__ emb) {
    // smem: Et[64][64] (emb transposed, [d][m]) then Ft[64][128] ([d][n]).
    // After GEMM, the same buffer is reused for scores S[64][132] (stride 132
    // breaks the 32-way bank conflict of the per-m row scan down to 4-way).
    __shared__ float sm[64 * 64 + 64 * 128];
    float* Et = sm;
    float* Ft = sm + 64 * 64;

    const int tile = blockIdx.x;
    const int b    = blockIdx.y;
    const int tid  = threadIdx.x;
    const int n0   = tile * TN;

    // Load emb [M][D] -> Et[d][m]
    for (int i = tid; i < MM * DD; i += 128) {
        int m = i >> 6, d = i & 63;
        Et[d * 64 + m] = emb[i];
    }
    // Load feat tile [TN][D] -> Ft[d][j]
    const float* fb = feat + (size_t)b * NN * DD;
    for (int i = tid; i < TN * DD; i += 128) {
        int j = i >> 6, d = i & 63;
        int n = n0 + j;
        Ft[d * 128 + j] = (n < NN) ? fb[(size_t)n * DD + d] : 0.0f;
    }
    __syncthreads();

    // 8x8 register-blocked GEMM: thread (mt, nt) owns m = mt*8..+7, n = nt*8..+7
    const int mt = tid >> 4;   // 0..7
    const int nt = tid & 15;   // 0..15

    float acc[8][8];
#pragma unroll
    for (int i = 0; i < 8; ++i)
#pragma unroll
        for (int j = 0; j < 8; ++j) acc[i][j] = 0.0f;

#pragma unroll 4
    for (int d = 0; d < 64; ++d) {
        float4 e0 = *(const float4*)&Et[d * 64 + mt * 8];
        float4 e1 = *(const float4*)&Et[d * 64 + mt * 8 + 4];
        float4 f0 = *(const float4*)&Ft[d * 128 + nt * 8];
        float4 f1 = *(const float4*)&Ft[d * 128 + nt * 8 + 4];
        float em[8] = {e0.x, e0.y, e0.z, e0.w, e1.x, e1.y, e1.z, e1.w};
        float fn[8] = {f0.x, f0.y, f0.z, f0.w, f1.x, f1.y, f1.z, f1.w};
#pragma unroll
        for (int i = 0; i < 8; ++i)
#pragma unroll
            for (int j = 0; j < 8; ++j) acc[i][j] += em[i] * fn[j];
    }
    __syncthreads();

    // Stage scores into smem, row stride 132
    float* S = sm;
#pragma unroll
    for (int i = 0; i < 8; ++i) {
        float4 w0 = make_float4(acc[i][0], acc[i][1], acc[i][2], acc[i][3]);
        float4 w1 = make_float4(acc[i][4], acc[i][5], acc[i][6], acc[i][7]);
        *(float4*)&S[(mt * 8 + i) * 132 + nt * 8]     = w0;
        *(float4*)&S[(mt * 8 + i) * 132 + nt * 8 + 4] = w1;
    }
    __syncthreads();

    // Per-m top-10 scan of this tile (64 threads, one m each)
    if (tid < MM) {
        const int m = tid;
        float vals[KK];
        int   idxs[KK];
#pragma unroll
        for (int k = 0; k < KK; ++k) { vals[k] = -CUDART_INF_F; idxs[k] = 0x7fffffff; }

        const int nvalid = min(TN, NN - n0);
        for (int j = 0; j < nvalid; ++j) {
            float v = S[m * 132 + j];
            insert10(vals, idxs, v, n0 + j);
        }

        size_t base = (((size_t)(b * MM + m)) * NTILES + tile) * KK;
#pragma unroll
        for (int k = 0; k < KK; ++k) {
            g_cand_val[base + k] = vals[k];
            g_cand_idx[base + k] = idxs[k];
        }
    }
}

// ---------------------------------------------------------------------------
// Phase 2+3 (fused): per (b,m) warp — merge 790 candidates to final top-10,
// write indices/batch_indices, gather selected features.
// ---------------------------------------------------------------------------
__global__ __launch_bounds__(32)
void phase2_kernel(const float* __restrict__ feat, float* __restrict__ out) {
    const int row  = blockIdx.x;          // b*M + m
    const int b    = row / MM;
    const int lane = threadIdx.x;

    __shared__ float sv[32 * KK];
    __shared__ int   si[32 * KK];
    __shared__ int   s_final[KK];

    float vals[KK];
    int   idxs[KK];
#pragma unroll
    for (int k = 0; k < KK; ++k) { vals[k] = -CUDART_INF_F; idxs[k] = 0x7fffffff; }

    const int total = NTILES * KK;        // 790
    const size_t base = (size_t)row * total;
    for (int c = lane; c < total; c += 32) {
        insert10(vals, idxs, g_cand_val[base + c], g_cand_idx[base + c]);
    }
#pragma unroll
    for (int k = 0; k < KK; ++k) {
        sv[lane * KK + k] = vals[k];
        si[lane * KK + k] = idxs[k];
    }
    __syncwarp();

    if (lane == 0) {
#pragma unroll
        for (int k = 0; k < KK; ++k) { vals[k] = -CUDART_INF_F; idxs[k] = 0x7fffffff; }
        for (int c = 0; c < 32 * KK; ++c) {
            insert10(vals, idxs, sv[c], si[c]);
        }
#pragma unroll
        for (int k = 0; k < KK; ++k) {
            out[OFF_BI + (size_t)row * KK + k] = (float)b;
            out[OFF_ID + (size_t)row * KK + k] = (float)idxs[k];
            s_final[k] = idxs[k];
        }
    }
    __syncwarp();

    // Gather selected features: [row][k][0..63]
    const float* fb = feat + (size_t)b * NN * DD;
#pragma unroll
    for (int k = 0; k < KK; ++k) {
        int idx = s_final[k];
        float* dst = out + ((size_t)row * KK + k) * DD;
        const float* src = fb + (size_t)idx * DD;
        for (int d = lane; d < DD; d += 32) dst[d] = src[d];
    }
}

extern "C" void kernel_launch(void* const* d_in, const int* in_sizes, int n_in,
                              void* d_out, int out_size) {
    const float* feat = (const float*)d_in[0];   // [32,10000,64] fp32
    const float* emb  = (const float*)d_in[1];   // [64,64] fp32
    float* out = (float*)d_out;

    phase1_kernel<<<dim3(NTILES, BB), 128>>>(feat, emb);
    phase2_kernel<<<BB * MM, 32>>>(feat, out);
}

// round 2
// speedup vs baseline: 2.8376x; 2.8376x over previous
#include <cuda_runtime.h>
#include <math_constants.h>

#define BB 32
#define NN 10000
#define DD 64
#define MM 64
#define KK 10
#define TN 256
#define NTILES ((NN + TN - 1) / TN)   // 40
#define ROWS (BB * MM)                // 2048
#define CAP 1024
#define PITCH 68                      // floats per row in smem (272B, 16B aligned, conflict-free)

// Output layout (fp32 concat): selected [B,M,K,D] | batch_indices [B,M,K] | indices [B,M,K]
#define SEL_SIZE (BB * MM * KK * DD)
#define OFF_BI   (SEL_SIZE)
#define OFF_ID   (SEL_SIZE + BB * MM * KK)

// Scratch
__device__ float g_thr_part[ROWS * 4];
__device__ int   g_cnt[ROWS];
__device__ float g_cand_val[ROWS * CAP];
__device__ int   g_cand_idx[ROWS * CAP];

// ---------------------------------------------------------------------------
// helpers
// ---------------------------------------------------------------------------
__device__ __forceinline__ bool cand_gt(float v1, int i1, float v2, int i2) {
    return (v1 > v2) || (v1 == v2 && i1 < i2);   // desc by value, ties -> smaller idx
}

__device__ __forceinline__ void insert10(float (&vals)[KK], int (&idxs)[KK], float v, int i) {
    if (cand_gt(v, i, vals[KK - 1], idxs[KK - 1])) {
        vals[KK - 1] = v;
        idxs[KK - 1] = i;
#pragma unroll
        for (int k = KK - 1; k > 0; --k) {
            if (cand_gt(vals[k], idxs[k], vals[k - 1], idxs[k - 1])) {
                float tv = vals[k]; vals[k] = vals[k - 1]; vals[k - 1] = tv;
                int   ti = idxs[k]; idxs[k] = idxs[k - 1]; idxs[k - 1] = ti;
            }
        }
    }
}

#define CASD(a, b) { if (v[a] < v[b]) { float t_ = v[a]; v[a] = v[b]; v[b] = t_; } }
__device__ __forceinline__ void sort8_desc(float (&v)[8]) {
    CASD(0,1) CASD(2,3) CASD(4,5) CASD(6,7)
    CASD(0,2) CASD(1,3) CASD(4,6) CASD(5,7)
    CASD(1,2) CASD(5,6)
    CASD(0,4) CASD(1,5) CASD(2,6) CASD(3,7)
    CASD(2,4) CASD(3,5)
    CASD(1,2) CASD(3,4) CASD(5,6)
}

// ---------------------------------------------------------------------------
// shared GEMM core: 64m x 256n x 64d, 256 threads.
// Warp w owns m = w*8..w*8+7 (broadcast Et reads); lane l owns n = l + 32*j.
// Both phase0 and phase1 use this exact code -> bitwise identical scores.
// ---------------------------------------------------------------------------
__device__ __forceinline__ void load_tiles(float* Et, float* Ft, const float* __restrict__ emb,
                                           const float* __restrict__ feat_b, int n0, int tid) {
#pragma unroll
    for (int i = 0; i < 4; ++i) {                 // 1024 float4 for Et
        int g = tid + 256 * i;
        int m = g >> 4, d4 = g & 15;
        *(float4*)&Et[m * PITCH + d4 * 4] = *(const float4*)&emb[m * DD + d4 * 4];
    }
#pragma unroll
    for (int i = 0; i < 16; ++i) {                // 4096 float4 for Ft
        int g = tid + 256 * i;
        int n = g >> 4, d4 = g & 15;
        int ng = n0 + n;
        float4 v = make_float4(0.f, 0.f, 0.f, 0.f);
        if (ng < NN) v = *(const float4*)&feat_b[(size_t)ng * DD + d4 * 4];
        *(float4*)&Ft[n * PITCH + d4 * 4] = v;
    }
}

__device__ __forceinline__ void gemm_8x8(const float* Et, const float* Ft,
                                         int w, int l, float acc[8][8]) {
#pragma unroll
    for (int i = 0; i < 8; ++i)
#pragma unroll
        for (int j = 0; j < 8; ++j) acc[i][j] = 0.f;

    const float* EtW = Et + (w * 8) * PITCH;
    for (int d4 = 0; d4 < 16; ++d4) {
        float4 f[8];
#pragma unroll
        for (int j = 0; j < 8; ++j)
            f[j] = *(const float4*)&Ft[(l + 32 * j) * PITCH + d4 * 4];
#pragma unroll
        for (int i = 0; i < 8; ++i) {
            float4 e = *(const float4*)&EtW[i * PITCH + d4 * 4];
#pragma unroll
            for (int j = 0; j < 8; ++j) {
                acc[i][j] = fmaf(e.x, f[j].x, acc[i][j]);
                acc[i][j] = fmaf(e.y, f[j].y, acc[i][j]);
                acc[i][j] = fmaf(e.z, f[j].z, acc[i][j]);
                acc[i][j] = fmaf(e.w, f[j].w, acc[i][j]);
            }
        }
    }
}

// ---------------------------------------------------------------------------
// phase0: tiles 0..3 (n < 1024). Per (row, tile): exact 10th value -> g_thr_part.
// Also zeroes per-row candidate counters.
// ---------------------------------------------------------------------------
extern "C" __global__ void __launch_bounds__(256, 2)
phase0_kernel(const float* __restrict__ feat, const float* __restrict__ emb) {
    extern __shared__ float sm[];
    float* Et = sm;
    float* Ft = sm + MM * PITCH;

    const int tile = blockIdx.x;   // 0..3
    const int b    = blockIdx.y;
    const int tid  = threadIdx.x;
    const int n0   = tile * TN;

    if (tile == 0 && tid < MM) g_cnt[b * MM + tid] = 0;

    load_tiles(Et, Ft, emb, feat + (size_t)b * NN * DD, n0, tid);
    __syncthreads();

    const int w = tid >> 5, l = tid & 31;
    float acc[8][8];
    gemm_8x8(Et, Ft, w, l, acc);

#pragma unroll
    for (int i = 0; i < 8; ++i) {
        float v[8];
#pragma unroll
        for (int j = 0; j < 8; ++j) v[j] = acc[i][j];
        sort8_desc(v);
        float tenth = -CUDART_INF_F;
#pragma unroll
        for (int r = 0; r < KK; ++r) {
            float mv = v[0];
#pragma unroll
            for (int off = 16; off > 0; off >>= 1)
                mv = fmaxf(mv, __shfl_xor_sync(0xffffffffu, mv, off));
            unsigned ball = __ballot_sync(0xffffffffu, v[0] == mv);
            int src = __ffs((int)ball) - 1;
            if (l == src) {
#pragma unroll
                for (int k = 0; k < 7; ++k) v[k] = v[k + 1];
                v[7] = -CUDART_INF_F;
            }
            tenth = mv;
        }
        if (l == 0) g_thr_part[(size_t)(b * MM + w * 8 + i) * 4 + tile] = tenth;
    }
}

// ---------------------------------------------------------------------------
// phase1: all 40 tiles. GEMM + threshold filter -> atomic append of survivors.
// ---------------------------------------------------------------------------
extern "C" __global__ void __launch_bounds__(256, 2)
phase1_kernel(const float* __restrict__ feat, const float* __restrict__ emb) {
    extern __shared__ float sm[];
    float* Et    = sm;
    float* Ft    = sm + MM * PITCH;
    float* s_thr = Ft + TN * PITCH;

    const int tile = blockIdx.x;   // 0..39
    const int b    = blockIdx.y;
    const int tid  = threadIdx.x;
    const int n0   = tile * TN;

    if (tid < MM) {
        float4 p = *(const float4*)&g_thr_part[(size_t)(b * MM + tid) * 4];
        float t = fmaxf(fmaxf(p.x, p.y), fmaxf(p.z, p.w));
        s_thr[tid] = t - fabsf(t) * 1e-6f - 1e-30f;   // ulp safety margin
    }

    load_tiles(Et, Ft, emb, feat + (size_t)b * NN * DD, n0, tid);
    __syncthreads();

    const int w = tid >> 5, l = tid & 31;
    float acc[8][8];
    gemm_8x8(Et, Ft, w, l, acc);

#pragma unroll
    for (int i = 0; i < 8; ++i) {
        const float t   = s_thr[w * 8 + i];
        const int   row = b * MM + w * 8 + i;
#pragma unroll
        for (int j = 0; j < 8; ++j) {
            int n = n0 + l + 32 * j;
            if (acc[i][j] >= t && n < NN) {
                int pos = atomicAdd(&g_cnt[row], 1);
                if (pos < CAP) {
                    g_cand_val[(size_t)row * CAP + pos] = acc[i][j];
                    g_cand_idx[(size_t)row * CAP + pos] = n;
                }
            }
        }
    }
}

// ---------------------------------------------------------------------------
// phase2: one warp per row (8 rows / 256-thread CTA): exact top-10 of
// candidates by (val desc, idx asc), write indices + gather features.
// ---------------------------------------------------------------------------
extern "C" __global__ void __launch_bounds__(256)
phase2_kernel(const float* __restrict__ feat, float* __restrict__ out) {
    const int w   = threadIdx.x >> 5;
    const int l   = threadIdx.x & 31;
    const int row = blockIdx.x * 8 + w;
    const int b   = row >> 6;

    __shared__ int s_sel[8][KK];

    int cnt = g_cnt[row];
    if (cnt > CAP) cnt = CAP;

    float vals[KK];
    int   idxs[KK];
#pragma unroll
    for (int k = 0; k < KK; ++k) { vals[k] = -CUDART_INF_F; idxs[k] = 0x7fffffff; }

    const size_t base = (size_t)row * CAP;
    for (int c = l; c < cnt; c += 32)
        insert10(vals, idxs, g_cand_val[base + c], g_cand_idx[base + c]);

#pragma unroll
    for (int r = 0; r < KK; ++r) {
        float bv = vals[0];
        int   bi = idxs[0];
#pragma unroll
        for (int off = 16; off > 0; off >>= 1) {
            float ov = __shfl_xor_sync(0xffffffffu, bv, off);
            int   oi = __shfl_xor_sync(0xffffffffu, bi, off);
            if (cand_gt(ov, oi, bv, bi)) { bv = ov; bi = oi; }
        }
        if (vals[0] == bv && idxs[0] == bi) {   // unique winner (idx unique)
#pragma unroll
            for (int k = 0; k < KK - 1; ++k) { vals[k] = vals[k + 1]; idxs[k] = idxs[k + 1]; }
            vals[KK - 1] = -CUDART_INF_F; idxs[KK - 1] = 0x7fffffff;
        }
        if (l == 0) {
            out[OFF_BI + (size_t)row * KK + r] = (float)b;
            out[OFF_ID + (size_t)row * KK + r] = (float)bi;
            s_sel[w][r] = bi;
        }
    }
    __syncwarp();

    const float* fb = feat + (size_t)b * NN * DD;
#pragma unroll
    for (int k = 0; k < KK; ++k) {
        const float2 v = *(const float2*)&fb[(size_t)s_sel[w][k] * DD + l * 2];
        *(float2*)&out[((size_t)row * KK + k) * DD + l * 2] = v;
    }
}

// ---------------------------------------------------------------------------
extern "C" void kernel_launch(void* const* d_in, const int* in_sizes, int n_in,
                              void* d_out, int out_size) {
    const float* feat = (const float*)d_in[0];   // [32,10000,64] fp32
    const float* emb  = (const float*)d_in[1];   // [64,64] fp32
    float* out = (float*)d_out;

    const int smem0 = (MM + TN) * PITCH * (int)sizeof(float);          // 87040
    const int smem1 = smem0 + MM * (int)sizeof(float);                 // +s_thr

    cudaFuncSetAttribute(phase0_kernel, cudaFuncAttributeMaxDynamicSharedMemorySize, smem0);
    cudaFuncSetAttribute(phase1_kernel, cudaFuncAttributeMaxDynamicSharedMemorySize, smem1);

    phase0_kernel<<<dim3(4, BB), 256, smem0>>>(feat, emb);
    phase1_kernel<<<dim3(NTILES, BB), 256, smem1>>>(feat, emb);
    phase2_kernel<<<ROWS / 8, 256>>>(feat, out);
}

// round 5
// speedup vs baseline: 3.4714x; 1.2234x over previous
#include <cuda_runtime.h>
#include <math_constants.h>
#include <cstdint>

#define BB 32
#define NN 10000
#define DD 64
#define MM 64
#define KK 10
#define ROWS (BB * MM)                 // 2048
#define TN 256
#define NT_FULL ((NN + TN - 1) / TN)   // 40
#define NT_SUB 8
#define SUB (NT_SUB * TN)              // 2048
#define CAP 512
#define MARGIN 0.30f
#define PITCH 68                       // floats; 68 % 32 == 4 -> conflict-free fragment LDS

// Output layout (fp32 concat): selected [B,M,K,D] | batch_indices [B,M,K] | indices [B,M,K]
#define SEL_SIZE (BB * MM * KK * DD)
#define OFF_BI   (SEL_SIZE)
#define OFF_ID   (SEL_SIZE + BB * MM * KK)

// Scratch
__device__ float g_sub[(size_t)BB * SUB * MM];   // [b][n][m], 16 MB
__device__ float g_thr[ROWS];
__device__ int   g_cnt[ROWS];
__device__ int   g_cand[ROWS * CAP];

// smem layout (floats): emb_s[64*PITCH] | feat_s[256*PITCH] | s_thr[64]
#define SM_EMB_F  0
#define SM_FEAT_F (MM * PITCH)
#define SM_THR_F  (SM_FEAT_F + TN * PITCH)
#define SMEM_FLOATS (SM_THR_F + 64)
#define SMEM_BYTES (SMEM_FLOATS * 4)   // 87,552 B

// ---------------------------------------------------------------------------
// helpers
// ---------------------------------------------------------------------------
__device__ __forceinline__ uint32_t f2tf32(float x) {
    uint32_t r;
    asm("cvt.rna.tf32.f32 %0, %1;" : "=r"(r) : "f"(x));
    return r;
}

__device__ __forceinline__ void mma_tf32(float* d, const uint32_t* a, uint32_t b0, uint32_t b1) {
    asm volatile(
        "mma.sync.aligned.m16n8k8.row.col.f32.tf32.tf32.f32 "
        "{%0,%1,%2,%3}, {%4,%5,%6,%7}, {%8,%9}, {%0,%1,%2,%3};"
        : "+f"(d[0]), "+f"(d[1]), "+f"(d[2]), "+f"(d[3])
        : "r"(a[0]), "r"(a[1]), "r"(a[2]), "r"(a[3]), "r"(b0), "r"(b1));
}

__device__ __forceinline__ bool cand_gt(float v1, int i1, float v2, int i2) {
    return (v1 > v2) || (v1 == v2 && i1 < i2);
}

// values-only descending insert
__device__ __forceinline__ void insert_v(float (&vals)[KK], float v) {
    if (v > vals[KK - 1]) {
        vals[KK - 1] = v;
#pragma unroll
        for (int k = KK - 1; k > 0; --k)
            if (vals[k] > vals[k - 1]) { float t = vals[k]; vals[k] = vals[k - 1]; vals[k - 1] = t; }
    }
}

// ---------------------------------------------------------------------------
// tile load: fp32 gmem -> tf32-rounded bits in smem (row-major, pitch 68)
// ---------------------------------------------------------------------------
__device__ __forceinline__ void load_tiles(float* __restrict__ smem,
                                           const float* __restrict__ feat_b,
                                           const float* __restrict__ emb,
                                           int n0, int tid) {
    float* emb_s  = smem + SM_EMB_F;
    float* feat_s = smem + SM_FEAT_F;

    const float4* f4 = (const float4*)feat_b;
#pragma unroll
    for (int i = 0; i < 16; ++i) {                 // 4096 float4: 256 rows x 16
        int idx = tid + (i << 8);
        int n = idx >> 4, k4 = idx & 15;
        int ng = n0 + n;
        float4 v = make_float4(0.f, 0.f, 0.f, 0.f);
        if (ng < NN) v = f4[(size_t)ng * 16 + k4];
        float* dst = feat_s + n * PITCH + k4 * 4;
        dst[0] = __uint_as_float(f2tf32(v.x));
        dst[1] = __uint_as_float(f2tf32(v.y));
        dst[2] = __uint_as_float(f2tf32(v.z));
        dst[3] = __uint_as_float(f2tf32(v.w));
    }
    const float4* e4 = (const float4*)emb;
#pragma unroll
    for (int i = 0; i < 4; ++i) {                  // 1024 float4: 64 rows x 16
        int idx = tid + (i << 8);
        int m = idx >> 4, k4 = idx & 15;
        float4 v = e4[m * 16 + k4];
        float* dst = emb_s + m * PITCH + k4 * 4;
        dst[0] = __uint_as_float(f2tf32(v.x));
        dst[1] = __uint_as_float(f2tf32(v.y));
        dst[2] = __uint_as_float(f2tf32(v.z));
        dst[3] = __uint_as_float(f2tf32(v.w));
    }
}

// ---------------------------------------------------------------------------
// warp GEMM: 32n x 64m x 64k. acc[mb][nb][r], element mapping:
//   n = nbase + mb*16 + (l>>2) + (r>=2 ? 8 : 0)
//   m = nb*8 + (l&3)*2 + (r&1)
// ---------------------------------------------------------------------------
__device__ __forceinline__ void warp_gemm(const float* __restrict__ As,
                                          const float* __restrict__ Bs,
                                          int l, float acc[2][8][4]) {
#pragma unroll
    for (int mb = 0; mb < 2; ++mb)
#pragma unroll
        for (int nb = 0; nb < 8; ++nb)
#pragma unroll
            for (int r = 0; r < 4; ++r) acc[mb][nb][r] = 0.f;

    const int gid = l >> 2, tig = l & 3;
#pragma unroll
    for (int k8 = 0; k8 < 8; ++k8) {
        uint32_t a[2][4];
#pragma unroll
        for (int mb = 0; mb < 2; ++mb) {
            const float* ap = As + mb * 16 * PITCH + k8 * 8;
            a[mb][0] = __float_as_uint(ap[gid * PITCH + tig]);
            a[mb][1] = __float_as_uint(ap[(gid + 8) * PITCH + tig]);
            a[mb][2] = __float_as_uint(ap[gid * PITCH + tig + 4]);
            a[mb][3] = __float_as_uint(ap[(gid + 8) * PITCH + tig + 4]);
        }
#pragma unroll
        for (int nb = 0; nb < 8; ++nb) {
            const float* bp = Bs + nb * 8 * PITCH + k8 * 8;
            uint32_t b0 = __float_as_uint(bp[gid * PITCH + tig]);
            uint32_t b1 = __float_as_uint(bp[gid * PITCH + tig + 4]);
#pragma unroll
            for (int mb = 0; mb < 2; ++mb)
                mma_tf32(acc[mb][nb], a[mb], b0, b1);
        }
    }
}

// ---------------------------------------------------------------------------
// phase0a: approx scores for first 2048 n -> g_sub[b][n][m]
// ---------------------------------------------------------------------------
extern "C" __global__ void __launch_bounds__(256, 2)
phase0a_kernel(const float* __restrict__ feat, const float* __restrict__ emb) {
    extern __shared__ float smem[];
    const int tile = blockIdx.x;   // 0..7
    const int b    = blockIdx.y;
    const int tid  = threadIdx.x;

    load_tiles(smem, feat + (size_t)b * NN * DD, emb, tile * TN, tid);
    __syncthreads();

    const int w = tid >> 5, l = tid & 31;
    float acc[2][8][4];
    warp_gemm(smem + SM_FEAT_F + w * 32 * PITCH, smem + SM_EMB_F, l, acc);

    const int nbase = tile * TN + w * 32;
    float* gs = g_sub + (size_t)b * SUB * MM;
#pragma unroll
    for (int mb = 0; mb < 2; ++mb) {
        int n0r = nbase + mb * 16 + (l >> 2);
#pragma unroll
        for (int nb = 0; nb < 8; ++nb) {
            int mcol = nb * 8 + (l & 3) * 2;
            *(float2*)&gs[(size_t)n0r * MM + mcol]       = make_float2(acc[mb][nb][0], acc[mb][nb][1]);
            *(float2*)&gs[(size_t)(n0r + 8) * MM + mcol] = make_float2(acc[mb][nb][2], acc[mb][nb][3]);
        }
    }
}

// ---------------------------------------------------------------------------
// phase0b: CTA per batch. Per m: 10th largest of 2048 -> threshold; zero cnt.
// ---------------------------------------------------------------------------
extern "C" __global__ void __launch_bounds__(256)
phase0b_kernel() {
    const int b  = blockIdx.x;
    const int t  = threadIdx.x;
    const int m  = t & 63;
    const int ns = t >> 6;   // 0..3

    float vals[KK];
#pragma unroll
    for (int k = 0; k < KK; ++k) vals[k] = -CUDART_INF_F;

    const float* gs = g_sub + (size_t)b * SUB * MM;
    for (int n = ns; n < SUB; n += 4)
        insert_v(vals, gs[(size_t)n * MM + m]);   // coalesced across the CTA

    __shared__ float s[64][4 * KK];
#pragma unroll
    for (int k = 0; k < KK; ++k) s[m][ns * KK + k] = vals[k];
    __syncthreads();

    if (t < 64) {
        float v[KK];
#pragma unroll
        for (int k = 0; k < KK; ++k) v[k] = -CUDART_INF_F;
        for (int c = 0; c < 4 * KK; ++c) insert_v(v, s[t][c]);
        g_thr[b * MM + t] = v[KK - 1] - MARGIN;
        g_cnt[b * MM + t] = 0;
    }
}

// ---------------------------------------------------------------------------
// phase1: all tiles, approx score vs threshold -> append candidate n indices
// ---------------------------------------------------------------------------
extern "C" __global__ void __launch_bounds__(256, 2)
phase1_kernel(const float* __restrict__ feat, const float* __restrict__ emb) {
    extern __shared__ float smem[];
    const int tile = blockIdx.x;   // 0..39
    const int b    = blockIdx.y;
    const int tid  = threadIdx.x;

    float* s_thr = smem + SM_THR_F;
    if (tid < MM) s_thr[tid] = g_thr[b * MM + tid];

    load_tiles(smem, feat + (size_t)b * NN * DD, emb, tile * TN, tid);
    __syncthreads();

    const int w = tid >> 5, l = tid & 31;
    float acc[2][8][4];
    warp_gemm(smem + SM_FEAT_F + w * 32 * PITCH, smem + SM_EMB_F, l, acc);

    const int nbase = tile * TN + w * 32;
#pragma unroll
    for (int mb = 0; mb < 2; ++mb) {
#pragma unroll
        for (int nb = 0; nb < 8; ++nb) {
#pragma unroll
            for (int r = 0; r < 4; ++r) {
                int n = nbase + mb * 16 + (l >> 2) + ((r >> 1) << 3);
                int m = nb * 8 + (l & 3) * 2 + (r & 1);
                float v = acc[mb][nb][r];
                if (n < NN && v >= s_thr[m]) {
                    int row = b * MM + m;
                    int pos = atomicAdd(&g_cnt[row], 1);
                    if (pos < CAP) g_cand[row * CAP + pos] = n;
                }
            }
        }
    }
}

// ---------------------------------------------------------------------------
// phase2: exact fp32 rescoring of candidates, top-10, outputs + gather
// ---------------------------------------------------------------------------
extern "C" __global__ void __launch_bounds__(256)
phase2_kernel(const float* __restrict__ feat, const float* __restrict__ emb,
              float* __restrict__ out) {
    const int w = threadIdx.x >> 5, l = threadIdx.x & 31;
    const int row = blockIdx.x * 8 + w;
    const int b = row >> 6, m = row & 63;

    __shared__ float s_emb[8][64];
    __shared__ int   s_sel[8][KK];

    ((float2*)s_emb[w])[l] = ((const float2*)(emb + m * DD))[l];
    __syncwarp();

    int cnt = g_cnt[row];
    if (cnt > CAP) cnt = CAP;

    float vals[KK];
    int   idxs[KK];
#pragma unroll
    for (int k = 0; k < KK; ++k) { vals[k] = -CUDART_INF_F; idxs[k] = 0x7fffffff; }

    const float4* ep = (const float4*)s_emb[w];
    const float*  fb = feat + (size_t)b * NN * DD;
    for (int c = l; c < cnt; c += 32) {
        int n = g_cand[row * CAP + c];
        const float4* fp = (const float4*)(fb + (size_t)n * DD);
        float acc = 0.f;
#pragma unroll
        for (int q = 0; q < 16; ++q) {
            float4 f = fp[q];
            float4 e = ep[q];
            acc = fmaf(f.x, e.x, acc);
            acc = fmaf(f.y, e.y, acc);
            acc = fmaf(f.z, e.z, acc);
            acc = fmaf(f.w, e.w, acc);
        }
        if (cand_gt(acc, n, vals[KK - 1], idxs[KK - 1])) {
            vals[KK - 1] = acc; idxs[KK - 1] = n;
#pragma unroll
            for (int k = KK - 1; k > 0; --k)
                if (cand_gt(vals[k], idxs[k], vals[k - 1], idxs[k - 1])) {
                    float tv = vals[k]; vals[k] = vals[k - 1]; vals[k - 1] = tv;
                    int   ti = idxs[k]; idxs[k] = idxs[k - 1]; idxs[k - 1] = ti;
                }
        }
    }

#pragma unroll
    for (int rnd = 0; rnd < KK; ++rnd) {
        float bv = vals[0];
        int   bi = idxs[0];
#pragma unroll
        for (int off = 16; off > 0; off >>= 1) {
            float ov = __shfl_xor_sync(0xffffffffu, bv, off);
            int   oi = __shfl_xor_sync(0xffffffffu, bi, off);
            if (cand_gt(ov, oi, bv, bi)) { bv = ov; bi = oi; }
        }
        if (vals[0] == bv && idxs[0] == bi) {   // unique winner (idx unique)
#pragma unroll
            for (int k = 0; k < KK - 1; ++k) { vals[k] = vals[k + 1]; idxs[k] = idxs[k + 1]; }
            vals[KK - 1] = -CUDART_INF_F; idxs[KK - 1] = 0x7fffffff;
        }
        if (l == 0) {
            out[OFF_BI + (size_t)row * KK + rnd] = (float)b;
            out[OFF_ID + (size_t)row * KK + rnd] = (float)bi;
            s_sel[w][rnd] = bi;
        }
    }
    __syncwarp();

#pragma unroll
    for (int k = 0; k < KK; ++k) {
        const float2 v = *(const float2*)&fb[(size_t)s_sel[w][k] * DD + l * 2];
        *(float2*)&out[((size_t)row * KK + k) * DD + l * 2] = v;
    }
}

// ---------------------------------------------------------------------------
extern "C" void kernel_launch(void* const* d_in, const int* in_sizes, int n_in,
                              void* d_out, int out_size) {
    const float* feat = (const float*)d_in[0];   // [32,10000,64] fp32
    const float* emb  = (const float*)d_in[1];   // [64,64] fp32
    float* out = (float*)d_out;

    cudaFuncSetAttribute(phase0a_kernel, cudaFuncAttributeMaxDynamicSharedMemorySize, SMEM_BYTES);
    cudaFuncSetAttribute(phase1_kernel,  cudaFuncAttributeMaxDynamicSharedMemorySize, SMEM_BYTES);

    phase0a_kernel<<<dim3(NT_SUB, BB), 256, SMEM_BYTES>>>(feat, emb);
    phase0b_kernel<<<BB, 256>>>();
    phase1_kernel<<<dim3(NT_FULL, BB), 256, SMEM_BYTES>>>(feat, emb);
    phase2_kernel<<<ROWS / 8, 256>>>(feat, emb, out);
}